// round 4
// baseline (speedup 1.0000x reference)
#include <cuda_runtime.h>
#include <cstdint>

#define D_DIM   128
#define BM      128
#define BN      128
#define TPB     256
#define SSTRIDE 132   // floats; 132*4B stride keeps 16B alignment for frag loads

typedef unsigned long long u64;

__device__ __forceinline__ u64 packdup(float a){
    u64 r; asm("mov.b64 %0, {%1, %1};" : "=l"(r) : "f"(a)); return r;
}
__device__ __forceinline__ void fma2(u64 &d, u64 a, u64 b){
    asm("fma.rn.f32x2 %0, %1, %2, %0;" : "+l"(d) : "l"(a), "l"(b));
}
__device__ __forceinline__ void unpack2(u64 v, float &lo, float &hi){
    asm("mov.b64 {%0, %1}, %2;" : "=f"(lo), "=f"(hi) : "l"(v));
}

__global__ __launch_bounds__(TPB, 1)
void vq_kernel(const float* __restrict__ x, const float* __restrict__ embed,
               float* __restrict__ outInd, float* __restrict__ outQ, int K)
{
    extern __shared__ float smem[];
    float* xs   = smem;                      // [D_DIM][SSTRIDE] transposed x tile
    float* es   = xs + D_DIM * SSTRIDE;      // [D_DIM][SSTRIDE] transposed e tile
    float* xn   = es + D_DIM * SSTRIDE;      // [BM] row norms
    float* en   = xn + BM;                   // [BN] code norms
    int*   sIdx = (int*)(en + BN);           // [BM] winning code per row

    const int t    = threadIdx.x;
    const int lane = t & 31, warp = t >> 5;
    const int tx   = t & 15, ty   = t >> 4;
    const int m0   = blockIdx.x * BM;

    // ---- load x tile transposed (conflict-light scalar path) + row norms ----
    for (int r = warp; r < BM; r += 8){
        const float* xr = x + (size_t)(m0 + r) * D_DIM;
        float v0 = xr[lane], v1 = xr[lane+32], v2 = xr[lane+64], v3 = xr[lane+96];
        xs[(lane     )*SSTRIDE + r] = v0;
        xs[(lane + 32)*SSTRIDE + r] = v1;
        xs[(lane + 64)*SSTRIDE + r] = v2;
        xs[(lane + 96)*SSTRIDE + r] = v3;
        float sq = v0*v0 + v1*v1 + v2*v2 + v3*v3;
        #pragma unroll
        for (int off = 16; off; off >>= 1) sq += __shfl_xor_sync(0xFFFFFFFFu, sq, off);
        if (lane == 0) xn[r] = sq;
    }

    const float NEGINF = __int_as_float(0xff800000);
    float runv[8]; int runi[8];
    #pragma unroll
    for (int i = 0; i < 8; i++){ runv[i] = NEGINF; runi[i] = 0; }

    for (int n0 = 0; n0 < K; n0 += BN){
        __syncthreads();   // previous compute done reading es
        // ---- load e tile transposed + code norms ----
        for (int r = warp; r < BN; r += 8){
            const float* er = embed + (size_t)(n0 + r) * D_DIM;
            float v0 = er[lane], v1 = er[lane+32], v2 = er[lane+64], v3 = er[lane+96];
            es[(lane     )*SSTRIDE + r] = v0;
            es[(lane + 32)*SSTRIDE + r] = v1;
            es[(lane + 64)*SSTRIDE + r] = v2;
            es[(lane + 96)*SSTRIDE + r] = v3;
            float sq = v0*v0 + v1*v1 + v2*v2 + v3*v3;
            #pragma unroll
            for (int off = 16; off; off >>= 1) sq += __shfl_xor_sync(0xFFFFFFFFu, sq, off);
            if (lane == 0) en[r] = sq;
        }
        __syncthreads();

        // ---- 128x128 score tile: 8x8 per thread as 8 rows x 4 f32x2 pairs ----
        u64 acc[8][4];
        #pragma unroll
        for (int i = 0; i < 8; i++)
            #pragma unroll
            for (int p = 0; p < 4; p++) acc[i][p] = 0ull;

        const float* xa = xs + ty * 4;
        const float* eb = es + tx * 4;
        #pragma unroll 4
        for (int k = 0; k < D_DIM; k++){
            float4 a0 = *(const float4*)(xa + (size_t)k * SSTRIDE);
            float4 a1 = *(const float4*)(xa + 64 + (size_t)k * SSTRIDE);
            ulonglong2 b0 = *(const ulonglong2*)(eb + (size_t)k * SSTRIDE);
            ulonglong2 b1 = *(const ulonglong2*)(eb + 64 + (size_t)k * SSTRIDE);
            float av[8] = {a0.x, a0.y, a0.z, a0.w, a1.x, a1.y, a1.z, a1.w};
            #pragma unroll
            for (int i = 0; i < 8; i++){
                u64 aa = packdup(av[i]);
                fma2(acc[i][0], aa, b0.x);
                fma2(acc[i][1], aa, b0.y);
                fma2(acc[i][2], aa, b1.x);
                fma2(acc[i][3], aa, b1.y);
            }
        }

        // ---- epilogue: score + per-row argmax (first-occurrence tie-break) ----
        float4 enA = *(const float4*)(en + tx * 4);
        float4 enB = *(const float4*)(en + 64 + tx * 4);
        float env[8] = {enA.x, enA.y, enA.z, enA.w, enB.x, enB.y, enB.z, enB.w};
        #pragma unroll
        for (int i = 0; i < 8; i++){
            int r = (i < 4) ? (ty*4 + i) : (64 + ty*4 + (i - 4));
            float xnr = xn[r];
            float bv = NEGINF; int bi = 0;
            #pragma unroll
            for (int p = 0; p < 4; p++){
                float s0, s1; unpack2(acc[i][p], s0, s1);
                int cbase = (p < 2) ? (tx*4 + 2*p) : (64 + tx*4 + 2*(p - 2));
                float sc0 = (2.0f * s0 - xnr) - env[2*p];
                float sc1 = (2.0f * s1 - xnr) - env[2*p + 1];
                int c0 = n0 + cbase, c1 = c0 + 1;
                if (sc0 > bv || (sc0 == bv && c0 < bi)) { bv = sc0; bi = c0; }
                if (sc1 > bv || (sc1 == bv && c1 < bi)) { bv = sc1; bi = c1; }
            }
            // butterfly over the 16 lanes sharing this row group
            #pragma unroll
            for (int off = 8; off; off >>= 1){
                float ov = __shfl_xor_sync(0xFFFFFFFFu, bv, off);
                int   oi = __shfl_xor_sync(0xFFFFFFFFu, bi, off);
                if (ov > bv || (ov == bv && oi < bi)) { bv = ov; bi = oi; }
            }
            // earlier tiles have smaller indices: strict > keeps first occurrence
            if (bv > runv[i] || (bv == runv[i] && bi < runi[i])) { runv[i] = bv; runi[i] = bi; }
        }
    }

    // ---- write indices (as float) + broadcast for dequant ----
    if (tx == 0){
        #pragma unroll
        for (int i = 0; i < 8; i++){
            int r = (i < 4) ? (ty*4 + i) : (64 + ty*4 + (i - 4));
            sIdx[r] = runi[i];
            outInd[m0 + r] = (float)runi[i];
        }
    }
    __syncthreads();

    // ---- dequantize: quantize[row] = embed[ind[row]] (L2-resident gather) ----
    for (int i = t; i < BM * 32; i += TPB){
        int r = i >> 5, c = i & 31;
        int code = sIdx[r];
        float4 v = *(const float4*)(embed + (size_t)code * D_DIM + c * 4);
        *(float4*)(outQ + (size_t)(m0 + r) * D_DIM + c * 4) = v;
    }
}

extern "C" void kernel_launch(void* const* d_in, const int* in_sizes, int n_in,
                              void* d_out, int out_size)
{
    const float* x     = (const float*)d_in[0];
    const float* embed = (const float*)d_in[1];
    float* out = (float*)d_out;

    int N = in_sizes[0] / D_DIM;   // 131072 rows
    int K = in_sizes[1] / D_DIM;   // 1024 codes

    size_t smem_bytes = (size_t)(2 * D_DIM * SSTRIDE + BM + BN) * sizeof(float)
                      + (size_t)BM * sizeof(int);   // 136,704 B

    cudaFuncSetAttribute(vq_kernel, cudaFuncAttributeMaxDynamicSharedMemorySize,
                         (int)smem_bytes);

    // out layout: [embed_ind (N floats)] then [quantize (N*128 floats)]
    vq_kernel<<<N / BM, TPB, smem_bytes>>>(x, embed, out, out + N, K);
}